// round 11
// baseline (speedup 1.0000x reference)
#include <cuda_runtime.h>
#include <cuda_bf16.h>
#include <cstdint>

// ---------------------------------------------------------------------------
// SPN neuron: B=32768, F=512, P=256 scope pairs, M=8 mixture components.
//
// Log2-domain quadratic form per (p,m):
//   t_m = A1*x1^2 + B1*x1 + A2*x2^2 + B2*x2 + C     (scaled by log2 e)
//   lse2 = mx + log2( sum_m 2^(t_m - mx) )
//   out[b] = ln(2) * sum_p lse2_p
//
// R10: the last unexplored cell of the measured matrix — fused prologue
// (saves the ~11us two-kernel split cost) + grid 1184 / occ 2 (the grid
// where the main loop measures 37.3-38.1us) + the proven scalar FFMA/ex2.f32
// inner loop (every packed-math variant at the 128-reg ceiling spilled:
// R4 f32x2 -> 50us, R9 f16x2 -> 53us).
// ---------------------------------------------------------------------------

#define LOG2E_F    1.4426950408889634f
#define LN2_F      0.6931471805599453f
#define LOG2_2PI_F 2.6514961294723187f   // log2(2*pi)

constexpr int PF   = 512;   // features
constexpr int PP   = 256;   // scope pairs
constexpr int PM   = 8;     // mixture components
constexpr int ROWS = 8;     // batch rows per chunk

__device__ __forceinline__ float ex2f(float v) {
    float r; asm("ex2.approx.ftz.f32 %0, %1;" : "=f"(r) : "f"(v)); return r;
}
__device__ __forceinline__ float lg2f(float v) {
    float r; asm("lg2.approx.ftz.f32 %0, %1;" : "=f"(r) : "f"(v)); return r;
}
__device__ __forceinline__ float rcpf(float v) {
    float r; asm("rcp.approx.ftz.f32 %0, %1;" : "=f"(r) : "f"(v)); return r;
}
__device__ __forceinline__ void cp16(uint32_t smem_dst, const void* gmem_src) {
    asm volatile("cp.async.cg.shared.global [%0], [%1], 16;\n"
                 :: "r"(smem_dst), "l"(gmem_src));
}
__device__ __forceinline__ void cp_commit() {
    asm volatile("cp.async.commit_group;\n" ::: "memory");
}
template <int N>
__device__ __forceinline__ void cp_wait() {
    asm volatile("cp.async.wait_group %0;\n" :: "n"(N) : "memory");
}

// ---------------------------------------------------------------------------
// Single fused kernel. blockDim = 256: thread == scope pair p.
// ---------------------------------------------------------------------------
__global__ __launch_bounds__(256, 2)
void spn_main_kernel(const float* __restrict__ x,
                     const float* __restrict__ mean,
                     const float* __restrict__ stdv,
                     const float* __restrict__ wts,
                     const int*   __restrict__ w32,   // raw scopes as words
                     float* __restrict__ out,
                     int nchunks)
{
    __shared__ float sx[2][ROWS][PF];
    __shared__ float sred[8][ROWS];

    const int tid  = threadIdx.x;
    const int p    = tid;
    const int lane = tid & 31;
    const int warp = tid >> 5;

    const int stride = gridDim.x;
    const uint32_t sbase = (uint32_t)__cvta_generic_to_shared(&sx[0][0][0]);

    // ---- kick off first chunk's stage immediately (overlaps prologue) ----
    int c = blockIdx.x;
    if (c < nchunks) {
        const char* src = (const char*)(x + (size_t)c * ROWS * PF);
        #pragma unroll
        for (int k = 0; k < 4; k++)
            cp16(sbase + (tid + k * 256) * 16, src + (tid + k * 256) * 16);
    }
    cp_commit();

    // ---- scopes dtype detection (parallel, one barrier) ----
    // int64 LE values in [0,512): every odd 32-bit word of the first 512
    // words is zero; an int32 permutation of 0..511 has ~255 nonzero odds.
    const int any_odd = __syncthreads_or(w32[2 * tid + 1] != 0);
    int s0, s1;
    if (any_odd) { s0 = w32[2 * p]; s1 = w32[2 * p + 1]; }   // int32
    else         { s0 = w32[4 * p]; s1 = w32[4 * p + 2]; }   // int64
    s0 &= (PF - 1);  s1 &= (PF - 1);

    // ---- per-thread coefficient computation (prologue-only, MUFU-lean) ----
    float A1[PM], B1[PM], A2[PM], B2[PM], Cc[PM];
    {
        float w[PM], wsum = 0.f;
        #pragma unroll
        for (int m = 0; m < PM; m++) { w[m] = wts[p * PM + m]; wsum += w[m]; }
        const float l2wsum = lg2f(wsum);
        #pragma unroll
        for (int m = 0; m < PM; m++) {
            int base = (p * PM + m) * 2;
            float mu1 = mean[base + 0], mu2 = mean[base + 1];
            float sd1 = stdv[base + 0], sd2 = stdv[base + 1];
            float r1 = rcpf(sd1), r2 = rcpf(sd2);
            float i1 = r1 * r1, i2 = r2 * r2;
            A1[m] = -0.5f * i1 * LOG2E_F;
            B1[m] =  mu1  * i1 * LOG2E_F;
            A2[m] = -0.5f * i2 * LOG2E_F;
            B2[m] =  mu2  * i2 * LOG2E_F;
            Cc[m] = -0.5f * LOG2E_F * (mu1 * mu1 * i1 + mu2 * mu2 * i2)
                    - lg2f(sd1 * sd2) - LOG2_2PI_F
                    + lg2f(w[m]) - l2wsum;
        }
    }

    // ---- main loop: double-buffered cp.async, scalar f32 math ----
    int buf = 0;
    for (; c < nchunks; c += stride, buf ^= 1) {
        int cn = c + stride;
        if (cn < nchunks) {
            const char* src = (const char*)(x + (size_t)cn * ROWS * PF);
            uint32_t dst = sbase + (uint32_t)(buf ^ 1) * (ROWS * PF * 4);
            #pragma unroll
            for (int k = 0; k < 4; k++)
                cp16(dst + (tid + k * 256) * 16, src + (tid + k * 256) * 16);
        }
        cp_commit();
        cp_wait<1>();          // current chunk's group has landed
        __syncthreads();       // visible to all; prev iter's sred consumed

        float acc[ROWS];
        #pragma unroll
        for (int r = 0; r < ROWS; r++) {
            float x1 = sx[buf][r][s0];
            float x2 = sx[buf][r][s1];
            float x1s = x1 * x1;
            float x2s = x2 * x2;

            float t[PM];
            #pragma unroll
            for (int m = 0; m < PM; m++) {
                float v = fmaf(B2[m], x2, Cc[m]);
                v = fmaf(A2[m], x2s, v);
                v = fmaf(B1[m], x1, v);
                v = fmaf(A1[m], x1s, v);
                t[m] = v;
            }
            float m01 = fmaxf(t[0], t[1]), m23 = fmaxf(t[2], t[3]);
            float m45 = fmaxf(t[4], t[5]), m67 = fmaxf(t[6], t[7]);
            float mx  = fmaxf(fmaxf(m01, m23), fmaxf(m45, m67));
            #pragma unroll
            for (int m = 0; m < PM; m++) t[m] = ex2f(t[m] - mx);
            float s = ((t[0] + t[1]) + (t[2] + t[3]))
                    + ((t[4] + t[5]) + (t[6] + t[7]));
            acc[r] = mx + lg2f(s);
        }

        // Reduce 256 per-pair contributions -> 1 value per row
        #pragma unroll
        for (int r = 0; r < ROWS; r++) {
            float v = acc[r];
            #pragma unroll
            for (int off = 16; off; off >>= 1)
                v += __shfl_xor_sync(0xffffffffu, v, off);
            if (lane == 0) sred[warp][r] = v;
        }
        __syncthreads();

        if (tid < ROWS) {
            float s = 0.f;
            #pragma unroll
            for (int w = 0; w < 8; w++) s += sred[w][tid];
            out[c * ROWS + tid] = s * LN2_F;
        }
        // No trailing barrier: next iter's top barrier (after cp_wait) orders
        // this iter's sred reads against next iter's sred writes, and the
        // cp.async issued at next-iter top targets the buffer whose last
        // reads were sealed by this iteration's mid barrier.
    }
}

// ---------------------------------------------------------------------------
// Launch. Inputs: x f32[32768*512], mean f32[256*8*2], std f32[256*8*2],
// weights f32[256*8], scopes int{32,64}[512]. Output f32[32768].
// ---------------------------------------------------------------------------
extern "C" void kernel_launch(void* const* d_in, const int* in_sizes, int n_in,
                              void* d_out, int out_size)
{
    const float* x      = (const float*)d_in[0];
    const float* mean   = (const float*)d_in[1];
    const float* stdv   = (const float*)d_in[2];
    const float* wts    = (const float*)d_in[3];
    const int*   w32    = (const int*)d_in[4];
    float*       out    = (float*)d_out;

    const int B = in_sizes[0] / PF;          // 32768
    const int nchunks = B / ROWS;            // 4096

    // Grid 1184: the grid where the main loop measures fastest (R3/R8).
    int blocks = 1184;
    if (blocks > nchunks) blocks = nchunks;
    spn_main_kernel<<<blocks, 256>>>(x, mean, stdv, wts, w32, out, nchunks);
}

// round 13
// speedup vs baseline: 1.4527x; 1.4527x over previous
#include <cuda_runtime.h>
#include <cuda_bf16.h>
#include <cstdint>

// ---------------------------------------------------------------------------
// SPN neuron: B=32768, F=512, P=256 scope pairs, M=8 mixture components.
//
// Log2-domain quadratic form per (p,m):
//   t_m = A1*x1^2 + B1*x1 + A2*x2^2 + B2*x2 + C     (scaled by log2 e)
//   lse2 = mx + log2( sum_m 2^(t_m - mx) )
//   out[b] = ln(2) * sum_p lse2_p
//
// R12 == R11 resubmitted (previous round was a broker/container infra
// failure, no kernel signal). Split design, both halves cheap:
//  - precompute <<<256,32>>>: warp per pair, fully parallel (ballot dtype
//    detection, lanes 0-7 do the 8 components). ~launch-overhead wall time.
//  - main kernel: exactly the measured-best 38.1us loop (grid 1184, occ 2,
//    coalesced g_coef loads into registers, double-buffered cp.async,
//    scalar FFMA + ex2.f32 — every packed-math variant spilled and lost).
// ---------------------------------------------------------------------------

#define LOG2E_F    1.4426950408889634f
#define LN2_F      0.6931471805599453f
#define LOG2_2PI_F 2.6514961294723187f   // log2(2*pi)

constexpr int PF   = 512;   // features
constexpr int PP   = 256;   // scope pairs
constexpr int PM   = 8;     // mixture components
constexpr int ROWS = 8;     // batch rows per chunk

__device__ float g_coef[5 * PM * PP];   // [j in 0..4][m][p], p fastest
__device__ int2  g_scope2[PP];          // per-pair (s0, s1)

__device__ __forceinline__ float ex2f(float v) {
    float r; asm("ex2.approx.ftz.f32 %0, %1;" : "=f"(r) : "f"(v)); return r;
}
__device__ __forceinline__ float lg2f(float v) {
    float r; asm("lg2.approx.ftz.f32 %0, %1;" : "=f"(r) : "f"(v)); return r;
}
__device__ __forceinline__ float rcpf(float v) {
    float r; asm("rcp.approx.ftz.f32 %0, %1;" : "=f"(r) : "f"(v)); return r;
}
__device__ __forceinline__ void cp16(uint32_t smem_dst, const void* gmem_src) {
    asm volatile("cp.async.cg.shared.global [%0], [%1], 16;\n"
                 :: "r"(smem_dst), "l"(gmem_src));
}
__device__ __forceinline__ void cp_commit() {
    asm volatile("cp.async.commit_group;\n" ::: "memory");
}
template <int N>
__device__ __forceinline__ void cp_wait() {
    asm volatile("cp.async.wait_group %0;\n" :: "n"(N) : "memory");
}

// ---------------------------------------------------------------------------
// Precompute: 256 blocks x 32 threads. Block p = scope pair p; lane m < 8
// computes component m's 5 coefficients. Fully parallel, no serial scans.
// ---------------------------------------------------------------------------
__global__ void spn_precompute_kernel(const float* __restrict__ mean,
                                      const float* __restrict__ stdv,
                                      const float* __restrict__ wts,
                                      const int*   __restrict__ w32)
{
    const int p    = blockIdx.x;
    const int lane = threadIdx.x;

    // dtype detection: int64 LE values in [0,512) have zero odd words; an
    // int32 permutation of 0..511 has at most ONE zero among words 1..63.
    unsigned odd = __ballot_sync(0xffffffffu, w32[2 * lane + 1] != 0);
    const bool is32 = (odd != 0);

    if (lane == 0) {
        int s0 = (is32 ? w32[2 * p] : w32[4 * p]) & (PF - 1);
        int s1 = (is32 ? w32[2 * p + 1] : w32[4 * p + 2]) & (PF - 1);
        g_scope2[p] = make_int2(s0, s1);
    }

    // weight sum across the 8 components (lanes 0-7; xor offsets 4,2,1
    // reduce within 8-lane groups, so lanes 0..7 all hold sum of lanes 0..7)
    float w = (lane < PM) ? wts[p * PM + lane] : 0.f;
    float wsum = w;
    #pragma unroll
    for (int off = 4; off; off >>= 1)
        wsum += __shfl_xor_sync(0xffffffffu, wsum, off);

    if (lane >= PM) return;
    const int m = lane;
    const float l2wsum = lg2f(wsum);

    int base = (p * PM + m) * 2;
    float mu1 = mean[base + 0], mu2 = mean[base + 1];
    float sd1 = stdv[base + 0], sd2 = stdv[base + 1];
    float r1 = rcpf(sd1), r2 = rcpf(sd2);
    float i1 = r1 * r1, i2 = r2 * r2;

    g_coef[(0 * PM + m) * PP + p] = -0.5f * i1 * LOG2E_F;
    g_coef[(1 * PM + m) * PP + p] =  mu1  * i1 * LOG2E_F;
    g_coef[(2 * PM + m) * PP + p] = -0.5f * i2 * LOG2E_F;
    g_coef[(3 * PM + m) * PP + p] =  mu2  * i2 * LOG2E_F;
    g_coef[(4 * PM + m) * PP + p] =
        -0.5f * LOG2E_F * (mu1 * mu1 * i1 + mu2 * mu2 * i2)
        - lg2f(sd1 * sd2) - LOG2_2PI_F + lg2f(w) - l2wsum;
}

// ---------------------------------------------------------------------------
// Main kernel: blockDim = 256 (thread == pair). Grid-stride over 8-row
// chunks, double-buffered cp.async staging. (R8's measured 38.1us loop.)
// ---------------------------------------------------------------------------
__global__ __launch_bounds__(256, 2)
void spn_main_kernel(const float* __restrict__ x,
                     float* __restrict__ out,
                     int nchunks)
{
    __shared__ float sx[2][ROWS][PF];
    __shared__ float sred[8][ROWS];

    const int tid  = threadIdx.x;
    const int lane = tid & 31;
    const int warp = tid >> 5;

    // Coefficients -> registers (coalesced: p is fastest dim of g_coef)
    float A1[PM], B1[PM], A2[PM], B2[PM], Cc[PM];
    #pragma unroll
    for (int m = 0; m < PM; m++) {
        A1[m] = g_coef[(0 * PM + m) * PP + tid];
        B1[m] = g_coef[(1 * PM + m) * PP + tid];
        A2[m] = g_coef[(2 * PM + m) * PP + tid];
        B2[m] = g_coef[(3 * PM + m) * PP + tid];
        Cc[m] = g_coef[(4 * PM + m) * PP + tid];
    }
    const int2 ss = g_scope2[tid];
    const int s0 = ss.x, s1 = ss.y;

    const int stride = gridDim.x;
    const uint32_t sbase = (uint32_t)__cvta_generic_to_shared(&sx[0][0][0]);

    // Prologue: stage first chunk into buffer 0.
    int c = blockIdx.x;
    if (c < nchunks) {
        const char* src = (const char*)(x + (size_t)c * ROWS * PF);
        #pragma unroll
        for (int k = 0; k < 4; k++)
            cp16(sbase + (tid + k * 256) * 16, src + (tid + k * 256) * 16);
    }
    cp_commit();

    int buf = 0;
    for (; c < nchunks; c += stride, buf ^= 1) {
        int cn = c + stride;
        if (cn < nchunks) {
            const char* src = (const char*)(x + (size_t)cn * ROWS * PF);
            uint32_t dst = sbase + (uint32_t)(buf ^ 1) * (ROWS * PF * 4);
            #pragma unroll
            for (int k = 0; k < 4; k++)
                cp16(dst + (tid + k * 256) * 16, src + (tid + k * 256) * 16);
        }
        cp_commit();
        cp_wait<1>();          // current chunk's group has landed
        __syncthreads();       // visible to all; prev iter's sred consumed

        float acc[ROWS];
        #pragma unroll
        for (int r = 0; r < ROWS; r++) {
            float x1 = sx[buf][r][s0];
            float x2 = sx[buf][r][s1];
            float x1s = x1 * x1;
            float x2s = x2 * x2;

            float t[PM];
            #pragma unroll
            for (int m = 0; m < PM; m++) {
                float v = fmaf(B2[m], x2, Cc[m]);
                v = fmaf(A2[m], x2s, v);
                v = fmaf(B1[m], x1, v);
                v = fmaf(A1[m], x1s, v);
                t[m] = v;
            }
            float m01 = fmaxf(t[0], t[1]), m23 = fmaxf(t[2], t[3]);
            float m45 = fmaxf(t[4], t[5]), m67 = fmaxf(t[6], t[7]);
            float mx  = fmaxf(fmaxf(m01, m23), fmaxf(m45, m67));
            #pragma unroll
            for (int m = 0; m < PM; m++) t[m] = ex2f(t[m] - mx);
            float s = ((t[0] + t[1]) + (t[2] + t[3]))
                    + ((t[4] + t[5]) + (t[6] + t[7]));
            acc[r] = mx + lg2f(s);
        }

        // Reduce 256 per-pair contributions -> 1 value per row
        #pragma unroll
        for (int r = 0; r < ROWS; r++) {
            float v = acc[r];
            #pragma unroll
            for (int off = 16; off; off >>= 1)
                v += __shfl_xor_sync(0xffffffffu, v, off);
            if (lane == 0) sred[warp][r] = v;
        }
        __syncthreads();

        if (tid < ROWS) {
            float s = 0.f;
            #pragma unroll
            for (int w = 0; w < 8; w++) s += sred[w][tid];
            out[c * ROWS + tid] = s * LN2_F;
        }
        // No trailing barrier: next iter's top barrier (after cp_wait) orders
        // this iter's sred reads against next iter's sred writes, and the
        // cp.async issued at next-iter top targets the buffer whose last
        // reads were sealed by this iteration's mid barrier.
    }
}

// ---------------------------------------------------------------------------
// Launch. Inputs: x f32[32768*512], mean f32[256*8*2], std f32[256*8*2],
// weights f32[256*8], scopes int{32,64}[512]. Output f32[32768].
// ---------------------------------------------------------------------------
extern "C" void kernel_launch(void* const* d_in, const int* in_sizes, int n_in,
                              void* d_out, int out_size)
{
    const float* x      = (const float*)d_in[0];
    const float* mean   = (const float*)d_in[1];
    const float* stdv   = (const float*)d_in[2];
    const float* wts    = (const float*)d_in[3];
    const int*   w32    = (const int*)d_in[4];
    float*       out    = (float*)d_out;

    const int B = in_sizes[0] / PF;          // 32768
    const int nchunks = B / ROWS;            // 4096

    spn_precompute_kernel<<<PP, 32>>>(mean, stdv, wts, w32);

    // Grid 1184: measured-best main-loop config (R3/R8: 37.3-38.1us).
    int blocks = 1184;
    if (blocks > nchunks) blocks = nchunks;
    spn_main_kernel<<<blocks, 256>>>(x, out, nchunks);
}

// round 14
// speedup vs baseline: 1.5585x; 1.0729x over previous
#include <cuda_runtime.h>
#include <cuda_bf16.h>
#include <cstdint>

// ---------------------------------------------------------------------------
// SPN neuron: B=32768, F=512, P=256 scope pairs, M=8 mixture components.
//
// Log2-domain quadratic form per (p,m):
//   t_m = A1*x1^2 + B1*x1 + A2*x2^2 + B2*x2 + C     (scaled by log2 e)
//   lse2 = mx + log2( sum_m 2^(t_m - mx) )
//   out[b] = ln(2) * sum_p lse2_p
//
// R13: R11 baseline (39.6us: warp-parallel precompute + 38.1us main loop)
// with the chunk-tail reduction restructured. Old: 8 rows x 5-deep shfl
// chains per warp (40 SHFL, 130-cyc serial chains) + warp-0-only finalize
// (barrier straggler every chunk). New: transpose through smem — 8 STS
// (conflict-free) + barrier + warp w sums row w with 8 stride-32 LDS +
// 7 FADD + one 5-level shuffle. Uniform work across warps, ~27 fewer
// warp-inst per chunk, no added register state.
// ---------------------------------------------------------------------------

#define LOG2E_F    1.4426950408889634f
#define LN2_F      0.6931471805599453f
#define LOG2_2PI_F 2.6514961294723187f   // log2(2*pi)

constexpr int PF   = 512;   // features
constexpr int PP   = 256;   // scope pairs
constexpr int PM   = 8;     // mixture components
constexpr int ROWS = 8;     // batch rows per chunk

__device__ float g_coef[5 * PM * PP];   // [j in 0..4][m][p], p fastest
__device__ int2  g_scope2[PP];          // per-pair (s0, s1)

__device__ __forceinline__ float ex2f(float v) {
    float r; asm("ex2.approx.ftz.f32 %0, %1;" : "=f"(r) : "f"(v)); return r;
}
__device__ __forceinline__ float lg2f(float v) {
    float r; asm("lg2.approx.ftz.f32 %0, %1;" : "=f"(r) : "f"(v)); return r;
}
__device__ __forceinline__ float rcpf(float v) {
    float r; asm("rcp.approx.ftz.f32 %0, %1;" : "=f"(r) : "f"(v)); return r;
}
__device__ __forceinline__ void cp16(uint32_t smem_dst, const void* gmem_src) {
    asm volatile("cp.async.cg.shared.global [%0], [%1], 16;\n"
                 :: "r"(smem_dst), "l"(gmem_src));
}
__device__ __forceinline__ void cp_commit() {
    asm volatile("cp.async.commit_group;\n" ::: "memory");
}
template <int N>
__device__ __forceinline__ void cp_wait() {
    asm volatile("cp.async.wait_group %0;\n" :: "n"(N) : "memory");
}

// ---------------------------------------------------------------------------
// Precompute: 256 blocks x 32 threads. Block p = scope pair p; lane m < 8
// computes component m's 5 coefficients. Fully parallel, no serial scans.
// ---------------------------------------------------------------------------
__global__ void spn_precompute_kernel(const float* __restrict__ mean,
                                      const float* __restrict__ stdv,
                                      const float* __restrict__ wts,
                                      const int*   __restrict__ w32)
{
    const int p    = blockIdx.x;
    const int lane = threadIdx.x;

    // dtype detection: int64 LE values in [0,512) have zero odd words; an
    // int32 permutation of 0..511 has at most ONE zero among words 1..63.
    unsigned odd = __ballot_sync(0xffffffffu, w32[2 * lane + 1] != 0);
    const bool is32 = (odd != 0);

    if (lane == 0) {
        int s0 = (is32 ? w32[2 * p] : w32[4 * p]) & (PF - 1);
        int s1 = (is32 ? w32[2 * p + 1] : w32[4 * p + 2]) & (PF - 1);
        g_scope2[p] = make_int2(s0, s1);
    }

    // weight sum across the 8 components (xor offsets 4,2,1 reduce within
    // 8-lane groups, so lanes 0..7 all hold the sum of lanes 0..7)
    float w = (lane < PM) ? wts[p * PM + lane] : 0.f;
    float wsum = w;
    #pragma unroll
    for (int off = 4; off; off >>= 1)
        wsum += __shfl_xor_sync(0xffffffffu, wsum, off);

    if (lane >= PM) return;
    const int m = lane;
    const float l2wsum = lg2f(wsum);

    int base = (p * PM + m) * 2;
    float mu1 = mean[base + 0], mu2 = mean[base + 1];
    float sd1 = stdv[base + 0], sd2 = stdv[base + 1];
    float r1 = rcpf(sd1), r2 = rcpf(sd2);
    float i1 = r1 * r1, i2 = r2 * r2;

    g_coef[(0 * PM + m) * PP + p] = -0.5f * i1 * LOG2E_F;
    g_coef[(1 * PM + m) * PP + p] =  mu1  * i1 * LOG2E_F;
    g_coef[(2 * PM + m) * PP + p] = -0.5f * i2 * LOG2E_F;
    g_coef[(3 * PM + m) * PP + p] =  mu2  * i2 * LOG2E_F;
    g_coef[(4 * PM + m) * PP + p] =
        -0.5f * LOG2E_F * (mu1 * mu1 * i1 + mu2 * mu2 * i2)
        - lg2f(sd1 * sd2) - LOG2_2PI_F + lg2f(w) - l2wsum;
}

// ---------------------------------------------------------------------------
// Main kernel: blockDim = 256 (thread == pair). Grid-stride over 8-row
// chunks, double-buffered cp.async staging, transposed smem reduction.
// ---------------------------------------------------------------------------
__global__ __launch_bounds__(256, 2)
void spn_main_kernel(const float* __restrict__ x,
                     float* __restrict__ out,
                     int nchunks)
{
    __shared__ float sx[2][ROWS][PF];
    __shared__ float sred[ROWS][PP];   // [row][pair] transpose buffer

    const int tid  = threadIdx.x;
    const int lane = tid & 31;
    const int warp = tid >> 5;

    // Coefficients -> registers (coalesced: p is fastest dim of g_coef)
    float A1[PM], B1[PM], A2[PM], B2[PM], Cc[PM];
    #pragma unroll
    for (int m = 0; m < PM; m++) {
        A1[m] = g_coef[(0 * PM + m) * PP + tid];
        B1[m] = g_coef[(1 * PM + m) * PP + tid];
        A2[m] = g_coef[(2 * PM + m) * PP + tid];
        B2[m] = g_coef[(3 * PM + m) * PP + tid];
        Cc[m] = g_coef[(4 * PM + m) * PP + tid];
    }
    const int2 ss = g_scope2[tid];
    const int s0 = ss.x, s1 = ss.y;

    const int stride = gridDim.x;
    const uint32_t sbase = (uint32_t)__cvta_generic_to_shared(&sx[0][0][0]);

    // Prologue: stage first chunk into buffer 0.
    int c = blockIdx.x;
    if (c < nchunks) {
        const char* src = (const char*)(x + (size_t)c * ROWS * PF);
        #pragma unroll
        for (int k = 0; k < 4; k++)
            cp16(sbase + (tid + k * 256) * 16, src + (tid + k * 256) * 16);
    }
    cp_commit();

    int buf = 0;
    for (; c < nchunks; c += stride, buf ^= 1) {
        int cn = c + stride;
        if (cn < nchunks) {
            const char* src = (const char*)(x + (size_t)cn * ROWS * PF);
            uint32_t dst = sbase + (uint32_t)(buf ^ 1) * (ROWS * PF * 4);
            #pragma unroll
            for (int k = 0; k < 4; k++)
                cp16(dst + (tid + k * 256) * 16, src + (tid + k * 256) * 16);
        }
        cp_commit();
        cp_wait<1>();          // current chunk's group has landed
        __syncthreads();       // visible to all; prev iter's sred consumed

        #pragma unroll
        for (int r = 0; r < ROWS; r++) {
            float x1 = sx[buf][r][s0];
            float x2 = sx[buf][r][s1];
            float x1s = x1 * x1;
            float x2s = x2 * x2;

            float t[PM];
            #pragma unroll
            for (int m = 0; m < PM; m++) {
                float v = fmaf(B2[m], x2, Cc[m]);
                v = fmaf(A2[m], x2s, v);
                v = fmaf(B1[m], x1, v);
                v = fmaf(A1[m], x1s, v);
                t[m] = v;
            }
            float m01 = fmaxf(t[0], t[1]), m23 = fmaxf(t[2], t[3]);
            float m45 = fmaxf(t[4], t[5]), m67 = fmaxf(t[6], t[7]);
            float mx  = fmaxf(fmaxf(m01, m23), fmaxf(m45, m67));
            #pragma unroll
            for (int m = 0; m < PM; m++) t[m] = ex2f(t[m] - mx);
            float s = ((t[0] + t[1]) + (t[2] + t[3]))
                    + ((t[4] + t[5]) + (t[6] + t[7]));
            // transpose store: lanes hit distinct banks (addr = r*256 + tid)
            sred[r][tid] = mx + lg2f(s);
        }
        __syncthreads();

        // Warp w sums row w over all 256 pairs: 8 stride-32 loads
        // (conflict-free) + tree add + 5-level shuffle. Uniform across warps.
        {
            float v0 = sred[warp][lane +   0] + sred[warp][lane +  32];
            float v1 = sred[warp][lane +  64] + sred[warp][lane +  96];
            float v2 = sred[warp][lane + 128] + sred[warp][lane + 160];
            float v3 = sred[warp][lane + 192] + sred[warp][lane + 224];
            float v  = (v0 + v1) + (v2 + v3);
            #pragma unroll
            for (int off = 16; off; off >>= 1)
                v += __shfl_xor_sync(0xffffffffu, v, off);
            if (lane == 0) out[c * ROWS + warp] = v * LN2_F;
        }
        // No trailing barrier: next iter's top barrier (after cp_wait) orders
        // this iter's sred reads against next iter's sred writes, and the
        // cp.async issued at next-iter top targets the buffer whose last
        // reads were sealed by this iteration's mid barrier.
    }
}

// ---------------------------------------------------------------------------
// Launch. Inputs: x f32[32768*512], mean f32[256*8*2], std f32[256*8*2],
// weights f32[256*8], scopes int{32,64}[512]. Output f32[32768].
// ---------------------------------------------------------------------------
extern "C" void kernel_launch(void* const* d_in, const int* in_sizes, int n_in,
                              void* d_out, int out_size)
{
    const float* x      = (const float*)d_in[0];
    const float* mean   = (const float*)d_in[1];
    const float* stdv   = (const float*)d_in[2];
    const float* wts    = (const float*)d_in[3];
    const int*   w32    = (const int*)d_in[4];
    float*       out    = (float*)d_out;

    const int B = in_sizes[0] / PF;          // 32768
    const int nchunks = B / ROWS;            // 4096

    spn_precompute_kernel<<<PP, 32>>>(mean, stdv, wts, w32);

    // Grid 1184: measured-best main-loop config (R3/R8/R12: 37.3-38.5us).
    int blocks = 1184;
    if (blocks > nchunks) blocks = nchunks;
    spn_main_kernel<<<blocks, 256>>>(x, out, nchunks);
}